// round 11
// baseline (speedup 1.0000x reference)
#include <cuda_runtime.h>
#include <math.h>

// Problem constants
#define HH 768
#define WW 768
#define NIMG 32
#define HWI (768 * 768)
#define HWLL (768LL * 768LL)

#define TW 128                 // columns per warp strip
#define ROWS 32                // output rows per warp
#define KTOT 36                // rows loaded per warp (ROWS + 4 halo)
#define CHUNKS (HH / ROWS)     // 24 row-chunks
#define BLOCKS_X (WW / TW)     // 6
#define WPI (BLOCKS_X * CHUNKS)  // 144 warp-partials per image

#define MIN_WEIGHT 0.1f

__device__ float g_part[NIMG * WPI];   // fully rewritten every run

__device__ __forceinline__ float tanh_a(float x) {
    float r;
    asm("tanh.approx.f32 %0, %1;" : "=f"(r) : "f"(x));
    return r;
}
__device__ __forceinline__ float sigm(float x) {
    return fmaf(0.5f, tanh_a(0.5f * x), 0.5f);
}

// ---- raw loads for row (gi0 + k - 2): own float4 + edge-lane 2-col halo ----
#define LOADROW(kk, Y, H0, H1)                                                  \
{                                                                               \
    const int gr = gi0 + (kk) - 2;                                              \
    Y = make_float4(0.f, 0.f, 0.f, 0.f); H0 = 0.f; H1 = 0.f;                    \
    if ((unsigned)gr < (unsigned)HH) {                                          \
        Y = *reinterpret_cast<const float4*>(yimg + gr * WW + gj0);             \
        if (eL & hasL) {                                                        \
            float2 t = *reinterpret_cast<const float2*>(yimg + gr * WW + col0 - 2); \
            H0 = t.x; H1 = t.y;                                                 \
        }                                                                       \
        if (eR & hasR) {                                                        \
            float2 t = *reinterpret_cast<const float2*>(yimg + gr * WW + col0 + TW); \
            H0 = t.x; H1 = t.y;                                                 \
        }                                                                       \
    }                                                                           \
}

// ---- process row k: sigmoid, shuffle halo, hs/hq, ring + running S/Q ----
#define PROCROW(kk, Y, H0, H1)                                                  \
{                                                                               \
    const int gr = gi0 + (kk) - 2;                                              \
    float4 p; float lz, lw, rx, ry;                                             \
    if ((unsigned)gr < (unsigned)HH) {                                          \
        p.x = sigm(Y.x); p.y = sigm(Y.y); p.z = sigm(Y.z); p.w = sigm(Y.w);     \
        const float s0 = sigm(H0), s1 = sigm(H1);                               \
        lz = __shfl_up_sync(0xffffffffu, p.z, 1);                               \
        lw = __shfl_up_sync(0xffffffffu, p.w, 1);                               \
        rx = __shfl_down_sync(0xffffffffu, p.x, 1);                             \
        ry = __shfl_down_sync(0xffffffffu, p.y, 1);                             \
        if (eL) { lz = hasL ? s0 : 0.f; lw = hasL ? s1 : 0.f; }                 \
        if (eR) { rx = hasR ? s0 : 0.f; ry = hasR ? s1 : 0.f; }                 \
    } else {                                                                    \
        p = make_float4(0.f, 0.f, 0.f, 0.f); lz = lw = rx = ry = 0.f;           \
    }                                                                           \
    float4 hs, hq;                                                              \
    hs.x = lz + lw + p.x + p.y + p.z;                                           \
    hs.y = hs.x - lz + p.w;                                                     \
    hs.z = hs.y - lw + rx;                                                      \
    hs.w = hs.z - p.x + ry;                                                     \
    const float qlz = lz*lz, qlw = lw*lw, qx = p.x*p.x, qy = p.y*p.y;           \
    const float qz = p.z*p.z, qw = p.w*p.w, qrx = rx*rx, qry = ry*ry;           \
    hq.x = qlz + qlw + qx + qy + qz;                                            \
    hq.y = hq.x - qlz + qw;                                                     \
    hq.z = hq.y - qlw + qrx;                                                    \
    hq.w = hq.z - qx + qry;                                                     \
    S.x += hs.x - hsR[(kk) % 5].x;  S.y += hs.y - hsR[(kk) % 5].y;              \
    S.z += hs.z - hsR[(kk) % 5].z;  S.w += hs.w - hsR[(kk) % 5].w;              \
    Q.x += hq.x - hqR[(kk) % 5].x;  Q.y += hq.y - hqR[(kk) % 5].y;              \
    Q.z += hq.z - hqR[(kk) % 5].z;  Q.w += hq.w - hqR[(kk) % 5].w;              \
    hsR[(kk) % 5] = hs;  hqR[(kk) % 5] = hq;                                    \
    pR[(kk) % 3] = p;                                                           \
}

__global__ __launch_bounds__(128, 4) void k_pass1(
    const float* __restrict__ yd,
    const float* __restrict__ ygt,
    float* __restrict__ out)
{
    const int lane = threadIdx.x & 31;
    const int wrp  = threadIdx.x >> 5;
    const int img  = blockIdx.z;
    const int col0 = blockIdx.x * TW;
    const int chunk = blockIdx.y * 4 + wrp;      // 0..23
    const int gi0  = chunk * ROWS;               // first output row
    const int gj0  = col0 + lane * 4;

    const float* __restrict__ yimg = yd  + (long long)img * HWLL;
    const float* __restrict__ gimg = ygt + (long long)img * HWLL;
    float* __restrict__ oimg = out + (long long)img * HWLL;

    const bool eL = (lane == 0), eR = (lane == 31);
    const bool hasL = (col0 > 0), hasR = (col0 + TW < WW);

    float fcx[4], rinvI[4];
    #pragma unroll
    for (int m = 0; m < 4; ++m) {
        const int gj = gj0 + m;
        fcx[m]   = (float)(min(gj, 2) + min(WW - 1 - gj, 2) + 1);
        rinvI[m] = __fdividef(1.0f, fcx[m] * 5.0f - 1.0f);
    }

    float4 hsR[5], hqR[5], pR[3];
    #pragma unroll
    for (int i = 0; i < 5; ++i) {
        hsR[i] = make_float4(0.f, 0.f, 0.f, 0.f);
        hqR[i] = make_float4(0.f, 0.f, 0.f, 0.f);
    }
    float4 S = make_float4(0.f, 0.f, 0.f, 0.f);
    float4 Q = make_float4(0.f, 0.f, 0.f, 0.f);

    // y_gt distance-2 prefetch ring (rows gi0, gi0+1 always in bounds)
    float4 gvR[2];
    gvR[0] = *reinterpret_cast<const float4*>(gimg + gi0 * WW + gj0);
    gvR[1] = *reinterpret_cast<const float4*>(gimg + (gi0 + 1) * WW + gj0);

    float lsum = 0.0f;

    float4 yc, yn; float hc0, hc1, hn0, hn1;
    LOADROW(0, yc, hc0, hc1)

    #pragma unroll
    for (int k = 0; k < KTOT; ++k) {
        if (k + 1 < KTOT) { LOADROW(k + 1, yn, hn0, hn1) }

        PROCROW(k, yc, hc0, hc1)

        if (k >= 4) {
            const int o   = k - 4;
            const int gro = gi0 + o;
            const float4 gv = gvR[o & 1];
            if (o + 2 < ROWS)
                gvR[o & 1] = *reinterpret_cast<const float4*>(gimg + (gro + 2) * WW + gj0);

            const float4 P0 = pR[(k - 2) % 3];
            const bool  yin = (gro >= 2) & (gro < HH - 2);   // warp-uniform
            const float fcy = yin ? 5.0f
                                  : (float)(min(gro, 2) + min(HH - 1 - gro, 2) + 1);

            float4 w;
            #define DO_COMP(c, mi)                                              \
            {                                                                   \
                const float fnv  = fcx[mi] * fcy;                               \
                const float rinv = yin ? rinvI[mi]                              \
                                       : __fdividef(1.0f, fnv - 1.0f);          \
                const float p0  = P0.c;                                         \
                const float acc = fmaf(fmaf(fnv, p0, -2.0f * S.c), p0, Q.c);    \
                const float cons = 1.0f - acc * rinv;                           \
                const float qq  = 1.0f - p0;                                    \
                const float l2p = __log2f(fmaxf(p0, 1e-37f));                   \
                const float l2q = __log2f(fmaxf(qq, 1e-37f));                   \
                const float ent = fmaf(p0, l2p, fmaf(qq, l2q, 1.0f));           \
                float ww = fmaxf(cons * ent, gv.c);                             \
                w.c = fmaf(1.0f - MIN_WEIGHT, ww, MIN_WEIGHT);                  \
            }
            DO_COMP(x, 0)
            DO_COMP(y, 1)
            DO_COMP(z, 2)
            DO_COMP(w, 3)
            #undef DO_COMP

            *reinterpret_cast<float4*>(oimg + gro * WW + gj0) = w;
            lsum += (w.x + w.y) + (w.z + w.w);
        }

        yc = yn; hc0 = hn0; hc1 = hn1;
    }

    // ---- warp reduction -> one partial per warp (no smem, no barrier) ----
    #pragma unroll
    for (int o = 16; o; o >>= 1) lsum += __shfl_down_sync(0xffffffffu, lsum, o);
    if (lane == 0)
        g_part[img * WPI + chunk * BLOCKS_X + blockIdx.x] = lsum;
}

// in-place per-image normalization: out *= HW / sum[img]; 8 float4 per thread
__global__ __launch_bounds__(256) void k_pass2(float* __restrict__ out) {
    const int img = blockIdx.y;
    float4* p = reinterpret_cast<float4*>(out + (long long)img * HWLL);
    const int tid  = threadIdx.x;
    const int base = blockIdx.x * 2048 + tid;

    // issue all 8 loads first (MLP=8) so they fly during the reduction
    float4 v0 = p[base];
    float4 v1 = p[base + 256];
    float4 v2 = p[base + 512];
    float4 v3 = p[base + 768];
    float4 v4 = p[base + 1024];
    float4 v5 = p[base + 1280];
    float4 v6 = p[base + 1536];
    float4 v7 = p[base + 1792];

    __shared__ float s_scale;
    if (tid < 32) {
        float v = 0.0f;
        #pragma unroll
        for (int t = 0; t < 5; ++t) {
            const int idx = tid + t * 32;
            if (idx < WPI) v += g_part[img * WPI + idx];
        }
        #pragma unroll
        for (int o = 16; o; o >>= 1) v += __shfl_down_sync(0xffffffffu, v, o);
        if (tid == 0) s_scale = __fdividef((float)HWI, v);
    }
    __syncthreads();
    const float s = s_scale;

    #define SC(v) v.x *= s; v.y *= s; v.z *= s; v.w *= s;
    SC(v0) SC(v1) SC(v2) SC(v3) SC(v4) SC(v5) SC(v6) SC(v7)
    #undef SC
    p[base]        = v0;
    p[base + 256]  = v1;
    p[base + 512]  = v2;
    p[base + 768]  = v3;
    p[base + 1024] = v4;
    p[base + 1280] = v5;
    p[base + 1536] = v6;
    p[base + 1792] = v7;
}

extern "C" void kernel_launch(void* const* d_in, const int* in_sizes, int n_in,
                              void* d_out, int out_size) {
    const float* yd  = (const float*)d_in[0];
    const float* ygt = (const float*)d_in[1];
    float* out = (float*)d_out;

    dim3 b1(128);
    dim3 g1(BLOCKS_X, CHUNKS / 4, NIMG);    // (6, 6, 32) blocks of 4 warps
    k_pass1<<<g1, b1>>>(yd, ygt, out);

    dim3 g2(HWI / 4 / 2048, NIMG);          // (72, 32)
    k_pass2<<<g2, 256>>>(out);
}

// round 12
// speedup vs baseline: 1.0174x; 1.0174x over previous
#include <cuda_runtime.h>
#include <math.h>

// Problem constants
#define HH 768
#define WW 768
#define NIMG 32
#define HWI (768 * 768)
#define HWLL (768LL * 768LL)

#define TW 128                 // columns per warp strip
#define ROWS 16                // output rows per warp
#define KTOT 20                // rows loaded per warp (ROWS + 4 halo)
#define CHUNKS (HH / ROWS)     // 48 row-chunks
#define BLOCKS_X (WW / TW)     // 6
#define WPI (BLOCKS_X * CHUNKS)  // 288 warp-partials per image

#define MIN_WEIGHT 0.1f

__device__ float g_part[NIMG * WPI];   // fully rewritten every run

__device__ __forceinline__ float tanh_a(float x) {
    float r;
    asm("tanh.approx.f32 %0, %1;" : "=f"(r) : "f"(x));
    return r;
}
__device__ __forceinline__ float sigm(float x) {
    return fmaf(0.5f, tanh_a(0.5f * x), 0.5f);
}

// ---- load row (gi0 + kk - 2) into 3-slot ring; INB folds away the guard ----
#define LOADROW(kk, INB)                                                        \
{                                                                               \
    const int gr = gi0 + (kk) - 2;                                              \
    float4 Y = make_float4(0.f, 0.f, 0.f, 0.f); float H0 = 0.f, H1 = 0.f;       \
    if ((INB) || (unsigned)gr < (unsigned)HH) {                                 \
        Y = *reinterpret_cast<const float4*>(yimg + gr * WW + gj0);             \
        if (eL & hasL) {                                                        \
            float2 t = *reinterpret_cast<const float2*>(yimg + gr * WW + col0 - 2); \
            H0 = t.x; H1 = t.y;                                                 \
        }                                                                       \
        if (eR & hasR) {                                                        \
            float2 t = *reinterpret_cast<const float2*>(yimg + gr * WW + col0 + TW); \
            H0 = t.x; H1 = t.y;                                                 \
        }                                                                       \
    }                                                                           \
    yB[(kk) % 3] = Y; h0B[(kk) % 3] = H0; h1B[(kk) % 3] = H1;                   \
}

// ---- process row kk from the ring: sigmoid, shuffle halo, hs/hq, S/Q ----
#define PROCROW(kk, INB)                                                        \
{                                                                               \
    const int gr = gi0 + (kk) - 2;                                              \
    const float4 Y = yB[(kk) % 3];                                              \
    float4 p; float lz, lw, rx, ry;                                             \
    if ((INB) || (unsigned)gr < (unsigned)HH) {                                 \
        p.x = sigm(Y.x); p.y = sigm(Y.y); p.z = sigm(Y.z); p.w = sigm(Y.w);     \
        const float s0 = sigm(h0B[(kk) % 3]), s1 = sigm(h1B[(kk) % 3]);         \
        lz = __shfl_up_sync(0xffffffffu, p.z, 1);                               \
        lw = __shfl_up_sync(0xffffffffu, p.w, 1);                               \
        rx = __shfl_down_sync(0xffffffffu, p.x, 1);                             \
        ry = __shfl_down_sync(0xffffffffu, p.y, 1);                             \
        if (eL) { lz = hasL ? s0 : 0.f; lw = hasL ? s1 : 0.f; }                 \
        if (eR) { rx = hasR ? s0 : 0.f; ry = hasR ? s1 : 0.f; }                 \
    } else {                                                                    \
        p = make_float4(0.f, 0.f, 0.f, 0.f); lz = lw = rx = ry = 0.f;           \
    }                                                                           \
    float4 hs, hq;                                                              \
    hs.x = lz + lw + p.x + p.y + p.z;                                           \
    hs.y = hs.x - lz + p.w;                                                     \
    hs.z = hs.y - lw + rx;                                                      \
    hs.w = hs.z - p.x + ry;                                                     \
    const float qlz = lz*lz, qlw = lw*lw, qx = p.x*p.x, qy = p.y*p.y;           \
    const float qz = p.z*p.z, qw = p.w*p.w, qrx = rx*rx, qry = ry*ry;           \
    hq.x = qlz + qlw + qx + qy + qz;                                            \
    hq.y = hq.x - qlz + qw;                                                     \
    hq.z = hq.y - qlw + qrx;                                                    \
    hq.w = hq.z - qx + qry;                                                     \
    S.x += hs.x - hsR[(kk) % 5].x;  S.y += hs.y - hsR[(kk) % 5].y;              \
    S.z += hs.z - hsR[(kk) % 5].z;  S.w += hs.w - hsR[(kk) % 5].w;              \
    Q.x += hq.x - hqR[(kk) % 5].x;  Q.y += hq.y - hqR[(kk) % 5].y;              \
    Q.z += hq.z - hqR[(kk) % 5].z;  Q.w += hq.w - hqR[(kk) % 5].w;              \
    hsR[(kk) % 5] = hs;  hqR[(kk) % 5] = hq;                                    \
    pR[(kk) % 3] = p;                                                           \
}

__global__ __launch_bounds__(128, 4) void k_pass1(
    const float* __restrict__ yd,
    const float* __restrict__ ygt,
    float* __restrict__ out)
{
    const int lane = threadIdx.x & 31;
    const int wrp  = threadIdx.x >> 5;
    const int img  = blockIdx.z;
    const int col0 = blockIdx.x * TW;
    const int chunk = blockIdx.y * 4 + wrp;      // 0..47
    const int gi0  = chunk * ROWS;               // first output row
    const int gj0  = col0 + lane * 4;

    const float* __restrict__ yimg = yd  + (long long)img * HWLL;
    const float* __restrict__ gimg = ygt + (long long)img * HWLL;
    float* __restrict__ oimg = out + (long long)img * HWLL;

    const bool eL = (lane == 0), eR = (lane == 31);
    const bool hasL = (col0 > 0), hasR = (col0 + TW < WW);

    float fcx[4], rinvI[4];
    #pragma unroll
    for (int m = 0; m < 4; ++m) {
        const int gj = gj0 + m;
        fcx[m]   = (float)(min(gj, 2) + min(WW - 1 - gj, 2) + 1);
        rinvI[m] = __fdividef(1.0f, fcx[m] * 5.0f - 1.0f);
    }

    float4 hsR[5], hqR[5], pR[3];
    #pragma unroll
    for (int i = 0; i < 5; ++i) {
        hsR[i] = make_float4(0.f, 0.f, 0.f, 0.f);
        hqR[i] = make_float4(0.f, 0.f, 0.f, 0.f);
    }
    float4 S = make_float4(0.f, 0.f, 0.f, 0.f);
    float4 Q = make_float4(0.f, 0.f, 0.f, 0.f);

    // y_gt distance-2 prefetch ring (rows gi0, gi0+1 always in bounds)
    float4 gvR[2];
    gvR[0] = *reinterpret_cast<const float4*>(gimg + gi0 * WW + gj0);
    gvR[1] = *reinterpret_cast<const float4*>(gimg + (gi0 + 1) * WW + gj0);

    // y_d distance-2 prefetch ring (3 slots)
    float4 yB[3]; float h0B[3], h1B[3];
    LOADROW(0, false)
    LOADROW(1, false)

    float lsum = 0.0f;

    #pragma unroll
    for (int k = 0; k < KTOT; ++k) {
        // prefetch row k+2 (interior rows 2..KTOT-3 provably in bounds)
        if (k + 2 < KTOT) {
            LOADROW(k + 2, ((k + 2) >= 2) && ((k + 2) <= KTOT - 3))
        }

        PROCROW(k, (k >= 2) && (k <= KTOT - 3))

        if (k >= 4) {
            const int o   = k - 4;
            const int gro = gi0 + o;
            const float4 gv = gvR[o & 1];
            if (o + 2 < ROWS)
                gvR[o & 1] = *reinterpret_cast<const float4*>(gimg + (gro + 2) * WW + gj0);

            const float4 P0 = pR[(k - 2) % 3];
            const bool  yin = (gro >= 2) & (gro < HH - 2);   // warp-uniform
            const float fcy = yin ? 5.0f
                                  : (float)(min(gro, 2) + min(HH - 1 - gro, 2) + 1);

            float4 w;
            #define DO_COMP(c, mi)                                              \
            {                                                                   \
                const float fnv  = fcx[mi] * fcy;                               \
                const float rinv = yin ? rinvI[mi]                              \
                                       : __fdividef(1.0f, fnv - 1.0f);          \
                const float p0  = P0.c;                                         \
                const float acc = fmaf(fmaf(fnv, p0, -2.0f * S.c), p0, Q.c);    \
                const float cons = 1.0f - acc * rinv;                           \
                const float qq  = 1.0f - p0;                                    \
                const float l2p = __log2f(fmaxf(p0, 1e-37f));                   \
                const float l2q = __log2f(fmaxf(qq, 1e-37f));                   \
                const float ent = fmaf(p0, l2p, fmaf(qq, l2q, 1.0f));           \
                float ww = fmaxf(cons * ent, gv.c);                             \
                w.c = fmaf(1.0f - MIN_WEIGHT, ww, MIN_WEIGHT);                  \
            }
            DO_COMP(x, 0)
            DO_COMP(y, 1)
            DO_COMP(z, 2)
            DO_COMP(w, 3)
            #undef DO_COMP

            *reinterpret_cast<float4*>(oimg + gro * WW + gj0) = w;
            lsum += (w.x + w.y) + (w.z + w.w);
        }
    }

    // ---- warp reduction -> one partial per warp (no smem, no barrier) ----
    #pragma unroll
    for (int o = 16; o; o >>= 1) lsum += __shfl_down_sync(0xffffffffu, lsum, o);
    if (lane == 0)
        g_part[img * WPI + chunk * BLOCKS_X + blockIdx.x] = lsum;
}

// in-place per-image normalization: out *= HW / sum[img]; 8 float4 per thread
__global__ __launch_bounds__(256) void k_pass2(float* __restrict__ out) {
    const int img = blockIdx.y;
    float4* p = reinterpret_cast<float4*>(out + (long long)img * HWLL);
    const int tid  = threadIdx.x;
    const int base = blockIdx.x * 2048 + tid;

    // issue all 8 loads first (MLP=8) so they fly during the reduction
    float4 v0 = p[base];
    float4 v1 = p[base + 256];
    float4 v2 = p[base + 512];
    float4 v3 = p[base + 768];
    float4 v4 = p[base + 1024];
    float4 v5 = p[base + 1280];
    float4 v6 = p[base + 1536];
    float4 v7 = p[base + 1792];

    __shared__ float s_scale;
    if (tid < 32) {
        float v = 0.0f;
        #pragma unroll
        for (int t = 0; t < 9; ++t) {
            const int idx = tid + t * 32;
            if (idx < WPI) v += g_part[img * WPI + idx];
        }
        #pragma unroll
        for (int o = 16; o; o >>= 1) v += __shfl_down_sync(0xffffffffu, v, o);
        if (tid == 0) s_scale = __fdividef((float)HWI, v);
    }
    __syncthreads();
    const float s = s_scale;

    #define SC(v) v.x *= s; v.y *= s; v.z *= s; v.w *= s;
    SC(v0) SC(v1) SC(v2) SC(v3) SC(v4) SC(v5) SC(v6) SC(v7)
    #undef SC
    p[base]        = v0;
    p[base + 256]  = v1;
    p[base + 512]  = v2;
    p[base + 768]  = v3;
    p[base + 1024] = v4;
    p[base + 1280] = v5;
    p[base + 1536] = v6;
    p[base + 1792] = v7;
}

extern "C" void kernel_launch(void* const* d_in, const int* in_sizes, int n_in,
                              void* d_out, int out_size) {
    const float* yd  = (const float*)d_in[0];
    const float* ygt = (const float*)d_in[1];
    float* out = (float*)d_out;

    dim3 b1(128);
    dim3 g1(BLOCKS_X, CHUNKS / 4, NIMG);    // (6, 12, 32) blocks of 4 warps
    k_pass1<<<g1, b1>>>(yd, ygt, out);

    dim3 g2(HWI / 4 / 2048, NIMG);          // (72, 32)
    k_pass2<<<g2, 256>>>(out);
}